// round 15
// baseline (speedup 1.0000x reference)
#include <cuda_runtime.h>
#include <math.h>

#define BB 64
#define TT 512
#define HH 512
#define GG 2048          // 4*H
#define RECBLK 128
#define RECTHR 256

// ---- static device scratch (no cudaMalloc allowed) ----
__device__ float g_G[67108864];    // G^T: [col 0..2048)[r=t*64+b 0..32768)  (268 MB)
__device__ float g_H0T[16777216];  // layer-0 output archive: [u][r]          (64 MB)
__device__ float g_h[65536];       // h state double buffer: 2 x [b][u]
__device__ unsigned g_leaf[8 * 64];  // 8 leaf counters, 256B apart
__device__ unsigned g_root;
__device__ unsigned g_gen;

// ---- L2-scope sync primitives (no L1 flush) ----
__device__ __forceinline__ unsigned atomAddRel(unsigned* p) {
    unsigned old;
    asm volatile("atom.release.gpu.global.add.u32 %0, [%1], 1;"
                 : "=r"(old) : "l"(p) : "memory");
    return old;
}
__device__ __forceinline__ unsigned ldAcq(const unsigned* p) {
    unsigned v;
    asm volatile("ld.acquire.gpu.global.u32 %0, [%1];"
                 : "=r"(v) : "l"(p) : "memory");
    return v;
}
__device__ __forceinline__ void stRel(unsigned* p, unsigned v) {
    asm volatile("st.release.gpu.global.u32 [%0], %1;"
                 :: "l"(p), "r"(v) : "memory");
}

// ---- monotonic 2-level grid barrier (replay-safe: no resets) ----
__device__ __forceinline__ void gridBarrier() {
    __syncthreads();
    if (threadIdx.x == 0) {
        unsigned g = ldAcq(&g_gen);
        unsigned leaf = (blockIdx.x >> 4) << 6;
        unsigned old = atomAddRel(&g_leaf[leaf]);
        if (old == g * 16u + 15u) {
            unsigned o2 = atomAddRel(&g_root);
            if (o2 == g * 8u + 7u) {
                stRel(&g_gen, g + 1u);
            } else {
                while (ldAcq(&g_gen) == g) { }
            }
        } else {
            while (ldAcq(&g_gen) == g) { }
        }
    }
    __syncthreads();
}

__device__ __forceinline__ float sigmoidf_(float x) {
    return 1.0f / (1.0f + __expf(-x));
}
// fast tanh via MUFU-based expf (rel err ~1e-6): tanh(x) = 2/(1+e^{-2x}) - 1
__device__ __forceinline__ float tanhf_(float x) {
    return 2.0f / (1.0f + __expf(-2.0f * x)) - 1.0f;
}

__device__ __forceinline__ unsigned smem_u32(const void* p) {
    unsigned a;
    asm("{ .reg .u64 t; cvta.to.shared.u64 t, %1; cvt.u32.u64 %0, t; }"
        : "=r"(a) : "l"(p));
    return a;
}

// ============================================================
// Precompute GEMM (transposed output), FFMA2 inner loop (unchanged, passing):
//   Gt[col][r] = W[col][:] . Xrow(r)[:] + bih[col] + bhh[col]
//   M = col = 2048, N = r = 32768, K = 512.
// ============================================================
__global__ void __launch_bounds__(256) lstm_pregemm(
    const float* __restrict__ xin,
    const float* __restrict__ Wih,
    const float* __restrict__ bih,
    const float* __restrict__ bhh,
    int layer0)
{
    __shared__ __align__(16) float As[16][128];   // [k][m=col]
    __shared__ __align__(16) float Bs[16][128];   // [k][n=r]
    const int tid = threadIdx.x;
    const int rblk = blockIdx.x * 128;   // n
    const int mblk = blockIdx.y * 128;   // m (col)
    const int nx = tid & 15;
    const int mx = tid >> 4;

    unsigned long long acc[8][4];
    #pragma unroll
    for (int i = 0; i < 8; ++i)
        #pragma unroll
        for (int j = 0; j < 4; ++j) acc[i][j] = 0ull;

    const unsigned bsBase = smem_u32(Bs) + (unsigned)nx * 32u;

    for (int kc = 0; kc < 512; kc += 16) {
        #pragma unroll
        for (int jj = 0; jj < 2; ++jj) {
            int e = tid + jj * 256;
            int m = e >> 2;
            int kq = e & 3;
            float4 v = *(const float4*)(Wih + (size_t)(mblk + m) * 512 + kc + kq * 4);
            As[kq*4+0][m] = v.x; As[kq*4+1][m] = v.y;
            As[kq*4+2][m] = v.z; As[kq*4+3][m] = v.w;
        }
        if (layer0) {
            #pragma unroll
            for (int jj = 0; jj < 2; ++jj) {
                int e = tid + jj * 256;
                int n = e >> 2;
                int kq = e & 3;
                int r = rblk + n;
                const float* src = xin + (size_t)(((r & 63) << 9) + (r >> 6)) * 512;
                float4 v = *(const float4*)(src + kc + kq * 4);
                Bs[kq*4+0][n] = v.x; Bs[kq*4+1][n] = v.y;
                Bs[kq*4+2][n] = v.z; Bs[kq*4+3][n] = v.w;
            }
        } else {
            #pragma unroll
            for (int jj = 0; jj < 2; ++jj) {
                int e = tid + jj * 256;
                int k = e >> 5;
                int nq = e & 31;
                *(float4*)&Bs[k][nq * 4] =
                    *(const float4*)(g_H0T + (size_t)(kc + k) * 32768 + rblk + nq * 4);
            }
        }
        __syncthreads();
        #pragma unroll
        for (int k = 0; k < 16; ++k) {
            float a[8];
            *(float4*)(a)     = *(const float4*)&As[k][mx * 8];
            *(float4*)(a + 4) = *(const float4*)&As[k][mx * 8 + 4];
            unsigned long long b0, b1, b2, b3;
            unsigned ba = bsBase + (unsigned)k * 512u;
            asm("ld.shared.v2.u64 {%0,%1},[%2];" : "=l"(b0), "=l"(b1) : "r"(ba));
            asm("ld.shared.v2.u64 {%0,%1},[%2];" : "=l"(b2), "=l"(b3) : "r"(ba + 16u));
            #pragma unroll
            for (int i = 0; i < 8; ++i) {
                unsigned long long hh;
                asm("mov.b64 %0,{%1,%2};" : "=l"(hh) : "f"(a[i]), "f"(a[i]));
                asm("fma.rn.f32x2 %0,%1,%2,%0;" : "+l"(acc[i][0]) : "l"(hh), "l"(b0));
                asm("fma.rn.f32x2 %0,%1,%2,%0;" : "+l"(acc[i][1]) : "l"(hh), "l"(b1));
                asm("fma.rn.f32x2 %0,%1,%2,%0;" : "+l"(acc[i][2]) : "l"(hh), "l"(b2));
                asm("fma.rn.f32x2 %0,%1,%2,%0;" : "+l"(acc[i][3]) : "l"(hh), "l"(b3));
            }
        }
        __syncthreads();
    }

    #pragma unroll
    for (int i = 0; i < 8; ++i) {
        int col = mblk + mx * 8 + i;
        float bsum = bih[col] + bhh[col];
        float f[8];
        #pragma unroll
        for (int j = 0; j < 4; ++j)
            asm("mov.b64 {%0,%1},%2;" : "=f"(f[2*j]), "=f"(f[2*j+1]) : "l"(acc[i][j]));
        float* dst = g_G + (size_t)col * 32768 + rblk + nx * 8;
        float4 v0 = make_float4(f[0]+bsum, f[1]+bsum, f[2]+bsum, f[3]+bsum);
        float4 v1 = make_float4(f[4]+bsum, f[5]+bsum, f[6]+bsum, f[7]+bsum);
        *(float4*)dst = v0;
        *(float4*)(dst + 4) = v1;
    }
}

// ============================================================
// Persistent recurrent kernel v6: 128 CTAs x 256 threads.
// CTA j owns units u0=4j..4j+3 (16 gate-cols = 4 gates x 4 units).
// Thread = (bh = tid>>7, kr = (tid>>2)&31, cg = tid&3):
//   gate cg, units u0..u0+3, k in [kr*16, kr*16+16), b in [bh*32, bh*32+32).
// FFMA2 PAIRED OVER K: acc_c += {h[k],h[k+1]} x {w_c[k],w_c[k+1]}
//   -> zero packing movs (h pair = float4 register pair, w pairs preloaded).
// Weights: 4 cols x 8 k-pairs in registers (32 u64), loaded once.
// 8-buffer / 4-block-lookahead L2 load pipeline; G prefetched per step.
// Split-K: 2 shfl-xor rounds -> red[8][64][18]; c state in registers.
// ============================================================
__global__ void __launch_bounds__(RECTHR, 1) lstm_recurrent(
    const float* __restrict__ Whh,
    const float* __restrict__ h0,
    const float* __restrict__ c0,
    float* __restrict__ outSeq,   // layer1: [b][t][u]; layer0: null (writes g_H0T)
    float* __restrict__ hfin,
    float* __restrict__ cfin,
    int layer1)
{
    __shared__ __align__(16) float red[8][64][18];   // [s][b][col], col = gate*4+unit

    const int tid = threadIdx.x;
    const int bid = blockIdx.x;
    const int u0  = bid * 4;
    const int bh  = tid >> 7;            // b half
    const int kr  = (tid >> 2) & 31;     // k range index (16 k each)
    const int cg  = tid & 3;             // gate
    const int sIdx = kr >> 2;            // reduce slice 0..7
    const bool writer = ((tid & 12) == 0);   // kr % 4 == 0
    const int bC  = tid & 63;            // cell batch
    const int uu  = tid >> 6;            // cell unit offset

    // ---- persistent weights in registers as k-pairs ----
    // wk[c][kp] = { Whh[cg*512+u0+c][kr*16+2kp], Whh[...][kr*16+2kp+1] }
    unsigned long long wk[4][8];
    #pragma unroll
    for (int c = 0; c < 4; ++c) {
        const float2* wrow = (const float2*)(Whh + (size_t)(cg * 512 + u0 + c) * 512
                                                 + kr * 16);
        #pragma unroll
        for (int kp = 0; kp < 8; ++kp) {
            float2 v = wrow[kp];
            asm("mov.b64 %0,{%1,%2};" : "=l"(wk[c][kp]) : "f"(v.x), "f"(v.y));
        }
    }

    // init state
    {
        int idx = bid * RECTHR + tid;
        __stcg(&g_h[idx], h0[idx]);
    }
    float c_reg = c0[bC * HH + u0 + uu];

    const float* gPtr0 = g_G + (size_t)(0 * 512 + u0 + uu) * 32768 + bC;
    const float* gPtr1 = g_G + (size_t)(1 * 512 + u0 + uu) * 32768 + bC;
    const float* gPtr2 = g_G + (size_t)(2 * 512 + u0 + uu) * 32768 + bC;
    const float* gPtr3 = g_G + (size_t)(3 * 512 + u0 + uu) * 32768 + bC;

    gridBarrier();

    for (int t = 0; t < TT; ++t) {
        const float* hRead = g_h + (t & 1) * 32768;
        float* hWrite      = g_h + ((t + 1) & 1) * 32768;
        // float4 base for (b = bh*32 + bl): idx = (bh*32+bl)*128 + kr*4
        const float4* hb = (const float4*)hRead + (bh * 32) * 128 + kr * 4;

        // ---- prefetch this step's G values (DRAM latency hidden by GEMM) ----
        size_t go = (size_t)t * 64;
        float gpre0 = __ldcs(gPtr0 + go);
        float gpre1 = __ldcs(gPtr1 + go);
        float gpre2 = __ldcs(gPtr2 + go);
        float gpre3 = __ldcs(gPtr3 + go);

        float4 buf[8];

        #define LDC(slot, bl) do {                                  \
            const float4* _p = hb + (bl) * 128;                     \
            buf[slot].x = 0.f; /* dummy to quiet init warnings */   \
            buf[slot] = make_float4(0.f,0.f,0.f,0.f);               \
            buf[slot].x = __ldcg(&_p->x + 0), buf[slot].y = __ldcg(&_p->x + 1), \
            buf[slot].z = __ldcg(&_p->x + 2), buf[slot].w = __ldcg(&_p->x + 3); \
        } while (0)
        // NOTE: scalar ldcg of float4 members defeats vectorization; use proper:
        #undef LDC
        #define LDC(slot, bl) do { buf[slot] = __ldcg(hb + (bl) * 128); } while (0)
        // wait: one float4 = only 4 k. Need 16 k (4 float4) per block. Use 2 slots
        // of float4 per... -> keep 4 float4 per block via 4 consecutive slots.
        #undef LDC

        // Each block bl needs 4 float4 (16 k). buf[8] holds 2 blocks.
        // Pipeline with explicit two-block granularity and 4-block lookahead
        // using two independent 8-float4 windows:
        float4 bufA[4], bufB[4], bufC[4], bufD[4], bufE[4], bufF[4];

        #define LD4(dst, bl) do {                                   \
            const float4* _p = hb + (bl) * 128;                     \
            dst[0] = __ldcg(_p);     dst[1] = __ldcg(_p + 1);       \
            dst[2] = __ldcg(_p + 2); dst[3] = __ldcg(_p + 3);       \
        } while (0)

        #define COMP(bufX, bl) do {                                             \
            unsigned long long _a0 = 0ull, _a1 = 0ull, _a2 = 0ull, _a3 = 0ull;  \
            _Pragma("unroll")                                                   \
            for (int _j = 0; _j < 4; ++_j) {                                    \
                float4 _hv = bufX[_j];                                          \
                unsigned long long _hp0, _hp1;                                  \
                asm("mov.b64 %0,{%1,%2};" : "=l"(_hp0) : "f"(_hv.x), "f"(_hv.y)); \
                asm("mov.b64 %0,{%1,%2};" : "=l"(_hp1) : "f"(_hv.z), "f"(_hv.w)); \
                asm("fma.rn.f32x2 %0,%1,%2,%0;" : "+l"(_a0) : "l"(_hp0), "l"(wk[0][_j*2])); \
                asm("fma.rn.f32x2 %0,%1,%2,%0;" : "+l"(_a1) : "l"(_hp0), "l"(wk[1][_j*2])); \
                asm("fma.rn.f32x2 %0,%1,%2,%0;" : "+l"(_a2) : "l"(_hp0), "l"(wk[2][_j*2])); \
                asm("fma.rn.f32x2 %0,%1,%2,%0;" : "+l"(_a3) : "l"(_hp0), "l"(wk[3][_j*2])); \
                asm("fma.rn.f32x2 %0,%1,%2,%0;" : "+l"(_a0) : "l"(_hp1), "l"(wk[0][_j*2+1])); \
                asm("fma.rn.f32x2 %0,%1,%2,%0;" : "+l"(_a1) : "l"(_hp1), "l"(wk[1][_j*2+1])); \
                asm("fma.rn.f32x2 %0,%1,%2,%0;" : "+l"(_a2) : "l"(_hp1), "l"(wk[2][_j*2+1])); \
                asm("fma.rn.f32x2 %0,%1,%2,%0;" : "+l"(_a3) : "l"(_hp1), "l"(wk[3][_j*2+1])); \
            }                                                                   \
            float _e0, _o0, _e1, _o1, _e2, _o2, _e3, _o3;                       \
            asm("mov.b64 {%0,%1},%2;" : "=f"(_e0), "=f"(_o0) : "l"(_a0));       \
            asm("mov.b64 {%0,%1},%2;" : "=f"(_e1), "=f"(_o1) : "l"(_a1));       \
            asm("mov.b64 {%0,%1},%2;" : "=f"(_e2), "=f"(_o2) : "l"(_a2));       \
            asm("mov.b64 {%0,%1},%2;" : "=f"(_e3), "=f"(_o3) : "l"(_a3));       \
            float _s0 = _e0 + _o0, _s1 = _e1 + _o1;                             \
            float _s2 = _e2 + _o2, _s3 = _e3 + _o3;                             \
            _s0 += __shfl_xor_sync(0xffffffffu, _s0, 4);                        \
            _s1 += __shfl_xor_sync(0xffffffffu, _s1, 4);                        \
            _s2 += __shfl_xor_sync(0xffffffffu, _s2, 4);                        \
            _s3 += __shfl_xor_sync(0xffffffffu, _s3, 4);                        \
            _s0 += __shfl_xor_sync(0xffffffffu, _s0, 8);                        \
            _s1 += __shfl_xor_sync(0xffffffffu, _s1, 8);                        \
            _s2 += __shfl_xor_sync(0xffffffffu, _s2, 8);                        \
            _s3 += __shfl_xor_sync(0xffffffffu, _s3, 8);                        \
            if (writer) {                                                       \
                float* _r = &red[sIdx][bh * 32 + (bl)][cg * 4];                 \
                *(float2*)_r       = make_float2(_s0, _s1);                     \
                *(float2*)(_r + 2) = make_float2(_s2, _s3);                     \
            }                                                                   \
        } while (0)

        // 4-block lookahead pipeline over 32 b-blocks
        LD4(bufA, 0); LD4(bufB, 1); LD4(bufC, 2); LD4(bufD, 3);
        for (int bl = 0; bl < 32; bl += 2) {
            if (bl + 4 < 32) { LD4(bufE, bl + 4); LD4(bufF, bl + 5); }
            COMP(bufA, bl);
            COMP(bufB, bl + 1);
            // rotate windows (register moves; compiler renames, fully unrolled)
            #pragma unroll
            for (int _i = 0; _i < 4; ++_i) {
                bufA[_i] = bufC[_i]; bufB[_i] = bufD[_i];
                bufC[_i] = bufE[_i]; bufD[_i] = bufF[_i];
            }
        }
        #undef LD4
        #undef COMP

        __syncthreads();

        // ---- cell update (thread owns (bC, u0+uu); c in register) ----
        {
            float v0 = gpre0, v1 = gpre1, v2 = gpre2, v3 = gpre3;
            #pragma unroll
            for (int s = 0; s < 8; ++s) {
                v0 += red[s][bC][0 * 4 + uu];
                v1 += red[s][bC][1 * 4 + uu];
                v2 += red[s][bC][2 * 4 + uu];
                v3 += red[s][bC][3 * 4 + uu];
            }
            float iv = sigmoidf_(v0);
            float fv = sigmoidf_(v1);
            float gv = tanhf_(v2);
            float ov = sigmoidf_(v3);
            c_reg = fv * c_reg + iv * gv;
            float hv = ov * tanhf_(c_reg);

            __stcg(&hWrite[bC * HH + u0 + uu], hv);
            if (layer1) outSeq[((size_t)bC * TT + t) * HH + u0 + uu] = hv;
            else        __stcg(&g_H0T[(size_t)(u0 + uu) * 32768 + (size_t)t * 64 + bC], hv);
            if (t == TT - 1) {
                hfin[bC * HH + u0 + uu] = hv;
                cfin[bC * HH + u0 + uu] = c_reg;
            }
        }
        gridBarrier();
    }
}

// ============================================================
// kernel_launch: 4 graph-capturable launches.
// Output: out [B,T,H] ++ h_fin [2,B,H] ++ c_fin [2,B,H]
// ============================================================
extern "C" void kernel_launch(void* const* d_in, const int* in_sizes, int n_in,
                              void* d_out, int out_size)
{
    (void)in_sizes; (void)n_in; (void)out_size;
    const float* x   = (const float*)d_in[0];
    const float* h0  = (const float*)d_in[1];
    const float* c0  = (const float*)d_in[2];
    const float* Wih = (const float*)d_in[3];
    const float* Whh = (const float*)d_in[4];
    const float* bih = (const float*)d_in[5];
    const float* bhh = (const float*)d_in[6];
    float* out  = (float*)d_out;
    float* hfin = out + (size_t)BB * TT * HH;
    float* cfin = hfin + 2 * BB * HH;

    dim3 pgrid(32768 / 128, GG / 128);   // (256, 16)

    // layer 0
    lstm_pregemm<<<pgrid, 256>>>(x, Wih, bih, bhh, 1);
    lstm_recurrent<<<RECBLK, RECTHR>>>(Whh, h0, c0, nullptr, hfin, cfin, 0);
    // layer 1 (input GEMM reads g_H0T directly)
    lstm_pregemm<<<pgrid, 256>>>(x, Wih + (size_t)GG * 512, bih + GG, bhh + GG, 0);
    lstm_recurrent<<<RECBLK, RECTHR>>>(Whh + (size_t)GG * 512,
                                       h0 + BB * HH, c0 + BB * HH,
                                       out, hfin + BB * HH, cfin + BB * HH, 1);
}